// round 15
// baseline (speedup 1.0000x reference)
#include <cuda_runtime.h>
#include <cstdint>

// Shapes (compile-time constants for this problem)
#define NB 8
#define CI 256
#define HH 64
#define WW 64
#define OC 256
#define KK 9
#define OH 64
#define OW 64
#define MTOT (NB * OH * OW)      // 32768
#define KC   (KK * CI)           // 2304

// Scratch (static device globals: allocation-free)
__device__ float g_xT[(size_t)NB * HH * WW * CI];        // channel-last x: [n][y][x][c]
__device__ float g_cols[(size_t)MTOT * KC];              // im2col [m][kc] (tf32-rounded)
__device__ float g_wt[(size_t)KC * OC];                  // transposed weight [kc][o] (tf32-rounded)

// ---------------------------------------------------------------------------
// Kernel 1: NCHW -> channel-last transpose of x
// ---------------------------------------------------------------------------
__global__ void transpose_x_kernel(const float* __restrict__ x) {
    __shared__ float tile[32][33];
    const int n  = blockIdx.z;
    const int p0 = blockIdx.x * 32;
    const int c0 = blockIdx.y * 32;
    const int tx = threadIdx.x, ty = threadIdx.y;
#pragma unroll
    for (int j = 0; j < 4; j++) {
        int c = c0 + ty + j * 8;
        tile[ty + j * 8][tx] = x[((size_t)(n * CI + c) << 12) + p0 + tx];
    }
    __syncthreads();
#pragma unroll
    for (int j = 0; j < 4; j++) {
        int p = p0 + ty + j * 8;
        g_xT[((size_t)n << 20) + ((size_t)p << 8) + c0 + tx] = tile[tx][ty + j * 8];
    }
}

// ---------------------------------------------------------------------------
// Kernel 2: weight transpose + tf32 rounding
// ---------------------------------------------------------------------------
__global__ void wt_kernel(const float* __restrict__ w) {
    const int kc = blockIdx.x;
    const int o  = threadIdx.x;
    const int k  = kc >> 8;
    const int c  = kc & 255;
    float v = w[(size_t)o * KC + c * KK + k];
    uint32_t u;
    asm("cvt.rna.tf32.f32 %0, %1;" : "=r"(u) : "f"(v));
    g_wt[(size_t)kc * OC + o] = __uint_as_float(u);
}

// ---------------------------------------------------------------------------
// Kernel 3: SMEM-windowed bilinear gather.
// One block = (n, oh) x 32-channel chunk. Stages input rows [oh-5, oh+5]
// (clamped) x full width x 32 ch into smem (row stride 36 floats), then all
// 9 taps x 64 ow interpolate from smem. Rare |offy|>~4 lanes fall back to
// global reads (identical arithmetic -> bit-identical results).
// L2 reads drop 1.18GB -> 0.37GB vs the per-warp gather.
// ---------------------------------------------------------------------------
#define WSTR 36
#define GATH_SMEM (11 * 64 * WSTR * 4)   // 101376 bytes

__global__ __launch_bounds__(512) void gather_kernel(const float* __restrict__ offset) {
    extern __shared__ float win[];       // [nrows][64][WSTR]
    const int tid = threadIdx.x;
    const int oh  = blockIdx.x;
    const int n   = blockIdx.y;
    const int c0  = blockIdx.z * 32;

    const int ylo = max(0, oh - 5);
    const int yhi = min(HH - 1, oh + 5);
    const int nrows = yhi - ylo + 1;

    const float* xb = g_xT + ((size_t)n << 20);

    // stage window: nrows*64*8 float4 chunks, coalesced
    const int nf4 = nrows * 512;         // 64*8 per row
    for (int i = tid; i < nf4; i += 512) {
        const int r = i >> 9;
        const int rem = i & 511;
        const int xx = rem >> 3;
        const int q  = rem & 7;
        float4 v = *(const float4*)(xb + ((((ylo + r) << 6) | xx) << 8) + c0 + q * 4);
        *(float4*)(win + (((r << 6) | xx) * WSTR) + q * 4) = v;
    }
    __syncthreads();

    const int ow    = tid >> 3;
    const int lane8 = tid & 7;
    const int l4    = lane8 * 4;
    const int p     = (oh << 6) | ow;
    const int m     = (n << 12) | p;

#pragma unroll
    for (int k = 0; k < KK; k++) {
        const float offy = __ldg(offset + (((size_t)(n * 18 + 2 * k)) << 12) + p);
        const float offx = __ldg(offset + (((size_t)(n * 18 + 2 * k + 1)) << 12) + p);

        const float yf = (float)(k / 3 - 1 + oh) + offy;
        const float xf = (float)(k % 3 - 1 + ow) + offx;
        const float y0f = floorf(yf), x0f = floorf(xf);
        const int y0 = (int)y0f, x0 = (int)x0f;
        const int y1 = y0 + 1,   x1 = x0 + 1;
        const float fy = yf - y0f, fx = xf - x0f;
        const float gy = 1.0f - fy, gx = 1.0f - fx;

        const bool vy0 = (y0 >= 0) & (y0 < HH);
        const bool vy1 = (y1 >= 0) & (y1 < HH);
        const bool vx0 = (x0 >= 0) & (x0 < WW);
        const bool vx1 = (x1 >= 0) & (x1 < WW);

        const float w00 = gy * gx * ((vy0 & vx0) ? 1.0f : 0.0f);
        const float w01 = gy * fx * ((vy0 & vx1) ? 1.0f : 0.0f);
        const float w10 = fy * gx * ((vy1 & vx0) ? 1.0f : 0.0f);
        const float w11 = fy * fx * ((vy1 & vx1) ? 1.0f : 0.0f);

        const int y0c = min(max(y0, 0), HH - 1), y1c = min(max(y1, 0), HH - 1);
        const int x0c = min(max(x0, 0), WW - 1), x1c = min(max(x1, 0), WW - 1);

        float4 a, b, d, e;
        if (y0c >= ylo && y1c <= yhi) {
            const int r0 = y0c - ylo, r1 = y1c - ylo;
            a = *(const float4*)(win + (((r0 << 6) | x0c) * WSTR) + l4);
            b = *(const float4*)(win + (((r0 << 6) | x1c) * WSTR) + l4);
            d = *(const float4*)(win + (((r1 << 6) | x0c) * WSTR) + l4);
            e = *(const float4*)(win + (((r1 << 6) | x1c) * WSTR) + l4);
        } else {
            const int c = c0 + l4;
            a = *(const float4*)(xb + (((y0c << 6) | x0c) << 8) + c);
            b = *(const float4*)(xb + (((y0c << 6) | x1c) << 8) + c);
            d = *(const float4*)(xb + (((y1c << 6) | x0c) << 8) + c);
            e = *(const float4*)(xb + (((y1c << 6) | x1c) << 8) + c);
        }

        float4 r;
        r.x = w00 * a.x + w01 * b.x + w10 * d.x + w11 * e.x;
        r.y = w00 * a.y + w01 * b.y + w10 * d.y + w11 * e.y;
        r.z = w00 * a.z + w01 * b.z + w10 * d.z + w11 * e.z;
        r.w = w00 * a.w + w01 * b.w + w10 * d.w + w11 * e.w;
        uint32_t u0, u1, u2, u3;
        asm("cvt.rna.tf32.f32 %0, %1;" : "=r"(u0) : "f"(r.x));
        asm("cvt.rna.tf32.f32 %0, %1;" : "=r"(u1) : "f"(r.y));
        asm("cvt.rna.tf32.f32 %0, %1;" : "=r"(u2) : "f"(r.z));
        asm("cvt.rna.tf32.f32 %0, %1;" : "=r"(u3) : "f"(r.w));
        r.x = __uint_as_float(u0); r.y = __uint_as_float(u1);
        r.z = __uint_as_float(u2); r.w = __uint_as_float(u3);
        __stcs((float4*)(g_cols + (size_t)m * KC + (k << 8) + c0 + l4), r);
    }
}

// ---------------------------------------------------------------------------
// Kernel 4: tf32 GEMM — R13 5-stage version (measured 209us, tensor 61%).
// ---------------------------------------------------------------------------
#define CP_ASYNC16(dst, src) \
    asm volatile("cp.async.cg.shared.global [%0], [%1], 16;\n" :: \
                 "r"((unsigned)__cvta_generic_to_shared(dst)), "l"(src))
#define CP_COMMIT() asm volatile("cp.async.commit_group;\n")
#define CP_WAIT3()  asm volatile("cp.async.wait_group 3;\n")

#define NKT (KC / 8)   // 288
#define NSTG 5
#define A_FLOATS (128 * 12)
#define B_FLOATS (8 * 136)
#define GEMM_SMEM (NSTG * (A_FLOATS + B_FLOATS) * 4)   // 52480 bytes

__global__ __launch_bounds__(128, 2) void gemm_kernel(float* __restrict__ out) {
    extern __shared__ float sm[];
    float (*As)[128][12] = (float(*)[128][12])sm;                    // [5][128][12]
    float (*Bs)[8][136]  = (float(*)[8][136])(sm + NSTG * A_FLOATS); // [5][8][136]

    const int t    = threadIdx.x;      // 0..127
    const int lane = t & 31, wid = t >> 5;
    const int warpM = wid >> 1, warpN = wid & 1;   // 2 x 2
    const int qid = lane >> 2, kq = lane & 3;
    const int bm = blockIdx.y * 128, bnn = blockIdx.x * 128;   // bx fastest = bn

    float acc[4][8][4];
#pragma unroll
    for (int a = 0; a < 4; a++)
#pragma unroll
        for (int b = 0; b < 8; b++)
#pragma unroll
            for (int c = 0; c < 4; c++) acc[a][b][c] = 0.0f;

    const int am0 = t >> 1, aseg = (t & 1) * 4;
    const int am1 = (t + 128) >> 1;
    const int aseg1 = ((t + 128) & 1) * 4;
    const int bk0 = t >> 5, bn0 = (t & 31) * 4;
    const int bk1 = (t + 128) >> 5, bn1 = bn0;

    // prologue: issue stages 0..3 (4 groups in flight)
#pragma unroll
    for (int s = 0; s < 4; s++) {
        CP_ASYNC16(&As[s][am0][aseg],  g_cols + (size_t)(bm + am0) * KC + s * 8 + aseg);
        CP_ASYNC16(&As[s][am1][aseg1], g_cols + (size_t)(bm + am1) * KC + s * 8 + aseg1);
        CP_ASYNC16(&Bs[s][bk0][bn0],   g_wt + (size_t)(s * 8 + bk0) * OC + bnn + bn0);
        CP_ASYNC16(&Bs[s][bk1][bn1],   g_wt + (size_t)(s * 8 + bk1) * OC + bnn + bn1);
        CP_COMMIT();
    }

    int cur = 0;       // kt % 5
    int nsl = 4;       // (kt+4) % 5
    for (int kt = 0; kt < NKT; ++kt) {
        CP_WAIT3();            // stage kt resident
        __syncthreads();

        {
            const int ks = (kt + 4 < NKT) ? (kt + 4) : (NKT - 1);
            CP_ASYNC16(&As[nsl][am0][aseg],  g_cols + (size_t)(bm + am0) * KC + ks * 8 + aseg);
            CP_ASYNC16(&As[nsl][am1][aseg1], g_cols + (size_t)(bm + am1) * KC + ks * 8 + aseg1);
            CP_ASYNC16(&Bs[nsl][bk0][bn0],   g_wt + (size_t)(ks * 8 + bk0) * OC + bnn + bn0);
            CP_ASYNC16(&Bs[nsl][bk1][bn1],   g_wt + (size_t)(ks * 8 + bk1) * OC + bnn + bn1);
            CP_COMMIT();
        }

        uint32_t bf[8][2];
#pragma unroll
        for (int ni = 0; ni < 8; ni++) {
            const int nb = warpN * 64 + ni * 8 + qid;
            bf[ni][0] = __float_as_uint(Bs[cur][kq][nb]);
            bf[ni][1] = __float_as_uint(Bs[cur][kq + 4][nb]);
        }
#pragma unroll
        for (int mi = 0; mi < 4; mi++) {
            const int mb = warpM * 64 + mi * 16 + qid;
            uint32_t a0 = __float_as_uint(As[cur][mb][kq]);
            uint32_t a1 = __float_as_uint(As[cur][mb + 8][kq]);
            uint32_t a2 = __float_as_uint(As[cur][mb][kq + 4]);
            uint32_t a3 = __float_as_uint(As[cur][mb + 8][kq + 4]);
#pragma unroll
            for (int ni = 0; ni < 8; ni++) {
                asm volatile(
                    "mma.sync.aligned.m16n8k8.row.col.f32.tf32.tf32.f32 "
                    "{%0,%1,%2,%3},{%4,%5,%6,%7},{%8,%9},{%0,%1,%2,%3};\n"
                    : "+f"(acc[mi][ni][0]), "+f"(acc[mi][ni][1]),
                      "+f"(acc[mi][ni][2]), "+f"(acc[mi][ni][3])
                    : "r"(a0), "r"(a1), "r"(a2), "r"(a3),
                      "r"(bf[ni][0]), "r"(bf[ni][1]));
            }
        }

        cur = (cur == NSTG - 1) ? 0 : cur + 1;
        nsl = (nsl == NSTG - 1) ? 0 : nsl + 1;
    }

    // epilogue: out[n][o][oh][ow]; m = n*4096 + p
#pragma unroll
    for (int mi = 0; mi < 4; mi++) {
#pragma unroll
        for (int h = 0; h < 2; h++) {
            const int m = bm + warpM * 64 + mi * 16 + qid + h * 8;
            const int nimg = m >> 12;
            const size_t base = ((size_t)nimg << 20) + (m & 4095);
#pragma unroll
            for (int ni = 0; ni < 8; ni++) {
                const int o = bnn + warpN * 64 + ni * 8 + kq * 2;
                out[base + (size_t)o * 4096]       = acc[mi][ni][h * 2 + 0];
                out[base + (size_t)(o + 1) * 4096] = acc[mi][ni][h * 2 + 1];
            }
        }
    }
}

// ---------------------------------------------------------------------------
extern "C" void kernel_launch(void* const* d_in, const int* in_sizes, int n_in,
                              void* d_out, int out_size) {
    const float* x      = (const float*)d_in[0];
    const float* offset = (const float*)d_in[1];
    const float* weight = (const float*)d_in[2];
    float* out = (float*)d_out;

    cudaFuncSetAttribute(gemm_kernel, cudaFuncAttributeMaxDynamicSharedMemorySize, GEMM_SMEM);
    cudaFuncSetAttribute(gather_kernel, cudaFuncAttributeMaxDynamicSharedMemorySize, GATH_SMEM);

    transpose_x_kernel<<<dim3(128, 8, 8), dim3(32, 8)>>>(x);
    wt_kernel<<<KC, 256>>>(weight);
    gather_kernel<<<dim3(OH, NB, 8), 512, GATH_SMEM>>>(offset);
    gemm_kernel<<<dim3(OC / 128, MTOT / 128), 128, GEMM_SMEM>>>(out);
}

// round 16
// speedup vs baseline: 1.1304x; 1.1304x over previous
#include <cuda_runtime.h>
#include <cstdint>

// Shapes (compile-time constants for this problem)
#define NB 8
#define CI 256
#define HH 64
#define WW 64
#define OC 256
#define KK 9
#define OH 64
#define OW 64
#define MTOT (NB * OH * OW)      // 32768
#define KC   (KK * CI)           // 2304

// Scratch (static device globals: allocation-free)
__device__ float g_xT[(size_t)NB * HH * WW * CI];        // channel-last x: [n][y][x][c]
__device__ float g_cols[(size_t)MTOT * KC];              // im2col [m][kc] (tf32-rounded)
__device__ float g_wt[(size_t)KC * OC];                  // transposed weight [kc][o] (tf32-rounded)

// ---------------------------------------------------------------------------
// Kernel 1: NCHW -> channel-last transpose of x
// ---------------------------------------------------------------------------
__global__ void transpose_x_kernel(const float* __restrict__ x) {
    __shared__ float tile[32][33];
    const int n  = blockIdx.z;
    const int p0 = blockIdx.x * 32;
    const int c0 = blockIdx.y * 32;
    const int tx = threadIdx.x, ty = threadIdx.y;
#pragma unroll
    for (int j = 0; j < 4; j++) {
        int c = c0 + ty + j * 8;
        tile[ty + j * 8][tx] = x[((size_t)(n * CI + c) << 12) + p0 + tx];
    }
    __syncthreads();
#pragma unroll
    for (int j = 0; j < 4; j++) {
        int p = p0 + ty + j * 8;
        g_xT[((size_t)n << 20) + ((size_t)p << 8) + c0 + tx] = tile[tx][ty + j * 8];
    }
}

// ---------------------------------------------------------------------------
// Kernel 2: weight transpose + tf32 rounding
// ---------------------------------------------------------------------------
__global__ void wt_kernel(const float* __restrict__ w) {
    const int kc = blockIdx.x;
    const int o  = threadIdx.x;
    const int k  = kc >> 8;
    const int c  = kc & 255;
    float v = w[(size_t)o * KC + c * KK + k];
    uint32_t u;
    asm("cvt.rna.tf32.f32 %0, %1;" : "=r"(u) : "f"(v));
    g_wt[(size_t)kc * OC + o] = __uint_as_float(u);
}

// ---------------------------------------------------------------------------
// Kernel 3: bilinear gather / im2col — one warp per m, tap loop INSIDE the
// warp. Cross-tap corner-row reuse becomes deterministic L1 temporal reuse
// (the 9 taps' 4x4-neighborhood rows are re-read by the SAME warp), and the
// 9 x 1KB stores per m are emitted consecutively by one warp (write
// combining). Arithmetic identical to R13 -> bit-identical cols.
// ---------------------------------------------------------------------------
__global__ __launch_bounds__(256) void gather_kernel(const float* __restrict__ offset) {
    const int m    = blockIdx.x * 8 + (threadIdx.x >> 5);
    const int lane = threadIdx.x & 31;
    const int n  = m >> 12;
    const int p  = m & 4095;
    const int oh = p >> 6;
    const int ow = p & 63;

    const float* xb = g_xT + ((size_t)n << 20);
    float* cp0 = g_cols + (size_t)m * KC;

#pragma unroll
    for (int k = 0; k < KK; k++) {
        const float offy = __ldg(offset + (((size_t)(n * 18 + 2 * k)) << 12) + p);
        const float offx = __ldg(offset + (((size_t)(n * 18 + 2 * k + 1)) << 12) + p);

        const float yf = (float)(k / 3 - 1 + oh) + offy;
        const float xf = (float)(k % 3 - 1 + ow) + offx;
        const float y0f = floorf(yf), x0f = floorf(xf);
        const int y0 = (int)y0f, x0 = (int)x0f;
        const int y1 = y0 + 1,   x1 = x0 + 1;
        const float fy = yf - y0f, fx = xf - x0f;
        const float gy = 1.0f - fy, gx = 1.0f - fx;

        const bool vy0 = (y0 >= 0) & (y0 < HH);
        const bool vy1 = (y1 >= 0) & (y1 < HH);
        const bool vx0 = (x0 >= 0) & (x0 < WW);
        const bool vx1 = (x1 >= 0) & (x1 < WW);

        const float w00 = gy * gx * ((vy0 & vx0) ? 1.0f : 0.0f);
        const float w01 = gy * fx * ((vy0 & vx1) ? 1.0f : 0.0f);
        const float w10 = fy * gx * ((vy1 & vx0) ? 1.0f : 0.0f);
        const float w11 = fy * fx * ((vy1 & vx1) ? 1.0f : 0.0f);

        const int y0c = min(max(y0, 0), HH - 1), y1c = min(max(y1, 0), HH - 1);
        const int x0c = min(max(x0, 0), WW - 1), x1c = min(max(x1, 0), WW - 1);

        const float* p00 = xb + (((y0c << 6) + x0c) << 8);
        const float* p01 = xb + (((y0c << 6) + x1c) << 8);
        const float* p10 = xb + (((y1c << 6) + x0c) << 8);
        const float* p11 = xb + (((y1c << 6) + x1c) << 8);

        float* cp = cp0 + (k << 8);

#pragma unroll
        for (int j = 0; j < 2; j++) {
            const int c = j * 128 + lane * 4;
            float4 a = *(const float4*)(p00 + c);
            float4 b = *(const float4*)(p01 + c);
            float4 d = *(const float4*)(p10 + c);
            float4 e = *(const float4*)(p11 + c);
            float4 r;
            r.x = w00 * a.x + w01 * b.x + w10 * d.x + w11 * e.x;
            r.y = w00 * a.y + w01 * b.y + w10 * d.y + w11 * e.y;
            r.z = w00 * a.z + w01 * b.z + w10 * d.z + w11 * e.z;
            r.w = w00 * a.w + w01 * b.w + w10 * d.w + w11 * e.w;
            uint32_t u0, u1, u2, u3;
            asm("cvt.rna.tf32.f32 %0, %1;" : "=r"(u0) : "f"(r.x));
            asm("cvt.rna.tf32.f32 %0, %1;" : "=r"(u1) : "f"(r.y));
            asm("cvt.rna.tf32.f32 %0, %1;" : "=r"(u2) : "f"(r.z));
            asm("cvt.rna.tf32.f32 %0, %1;" : "=r"(u3) : "f"(r.w));
            r.x = __uint_as_float(u0); r.y = __uint_as_float(u1);
            r.z = __uint_as_float(u2); r.w = __uint_as_float(u3);
            __stcs((float4*)(cp + c), r);
        }
    }
}

// ---------------------------------------------------------------------------
// Kernel 4: tf32 GEMM — R13 5-stage version, UNCHANGED (209us, tensor 61%,
// passed twice). 128x128 CTA tile, 4 warps (2x2), 64x64 warp tiles, K-step 8.
// ---------------------------------------------------------------------------
#define CP_ASYNC16(dst, src) \
    asm volatile("cp.async.cg.shared.global [%0], [%1], 16;\n" :: \
                 "r"((unsigned)__cvta_generic_to_shared(dst)), "l"(src))
#define CP_COMMIT() asm volatile("cp.async.commit_group;\n")
#define CP_WAIT3()  asm volatile("cp.async.wait_group 3;\n")

#define NKT (KC / 8)   // 288
#define NSTG 5
#define A_FLOATS (128 * 12)
#define B_FLOATS (8 * 136)
#define GEMM_SMEM (NSTG * (A_FLOATS + B_FLOATS) * 4)   // 52480 bytes

__global__ __launch_bounds__(128, 2) void gemm_kernel(float* __restrict__ out) {
    extern __shared__ float sm[];
    float (*As)[128][12] = (float(*)[128][12])sm;                    // [5][128][12]
    float (*Bs)[8][136]  = (float(*)[8][136])(sm + NSTG * A_FLOATS); // [5][8][136]

    const int t    = threadIdx.x;      // 0..127
    const int lane = t & 31, wid = t >> 5;
    const int warpM = wid >> 1, warpN = wid & 1;   // 2 x 2
    const int qid = lane >> 2, kq = lane & 3;
    const int bm = blockIdx.y * 128, bnn = blockIdx.x * 128;   // bx fastest = bn

    float acc[4][8][4];
#pragma unroll
    for (int a = 0; a < 4; a++)
#pragma unroll
        for (int b = 0; b < 8; b++)
#pragma unroll
            for (int c = 0; c < 4; c++) acc[a][b][c] = 0.0f;

    const int am0 = t >> 1, aseg = (t & 1) * 4;
    const int am1 = (t + 128) >> 1;
    const int aseg1 = ((t + 128) & 1) * 4;
    const int bk0 = t >> 5, bn0 = (t & 31) * 4;
    const int bk1 = (t + 128) >> 5, bn1 = bn0;

    // prologue: issue stages 0..3 (4 groups in flight)
#pragma unroll
    for (int s = 0; s < 4; s++) {
        CP_ASYNC16(&As[s][am0][aseg],  g_cols + (size_t)(bm + am0) * KC + s * 8 + aseg);
        CP_ASYNC16(&As[s][am1][aseg1], g_cols + (size_t)(bm + am1) * KC + s * 8 + aseg1);
        CP_ASYNC16(&Bs[s][bk0][bn0],   g_wt + (size_t)(s * 8 + bk0) * OC + bnn + bn0);
        CP_ASYNC16(&Bs[s][bk1][bn1],   g_wt + (size_t)(s * 8 + bk1) * OC + bnn + bn1);
        CP_COMMIT();
    }

    int cur = 0;       // kt % 5
    int nsl = 4;       // (kt+4) % 5
    for (int kt = 0; kt < NKT; ++kt) {
        CP_WAIT3();            // stage kt resident
        __syncthreads();

        {
            const int ks = (kt + 4 < NKT) ? (kt + 4) : (NKT - 1);
            CP_ASYNC16(&As[nsl][am0][aseg],  g_cols + (size_t)(bm + am0) * KC + ks * 8 + aseg);
            CP_ASYNC16(&As[nsl][am1][aseg1], g_cols + (size_t)(bm + am1) * KC + ks * 8 + aseg1);
            CP_ASYNC16(&Bs[nsl][bk0][bn0],   g_wt + (size_t)(ks * 8 + bk0) * OC + bnn + bn0);
            CP_ASYNC16(&Bs[nsl][bk1][bn1],   g_wt + (size_t)(ks * 8 + bk1) * OC + bnn + bn1);
            CP_COMMIT();
        }

        uint32_t bf[8][2];
#pragma unroll
        for (int ni = 0; ni < 8; ni++) {
            const int nb = warpN * 64 + ni * 8 + qid;
            bf[ni][0] = __float_as_uint(Bs[cur][kq][nb]);
            bf[ni][1] = __float_as_uint(Bs[cur][kq + 4][nb]);
        }
#pragma unroll
        for (int mi = 0; mi < 4; mi++) {
            const int mb = warpM * 64 + mi * 16 + qid;
            uint32_t a0 = __float_as_uint(As[cur][mb][kq]);
            uint32_t a1 = __float_as_uint(As[cur][mb + 8][kq]);
            uint32_t a2 = __float_as_uint(As[cur][mb][kq + 4]);
            uint32_t a3 = __float_as_uint(As[cur][mb + 8][kq + 4]);
#pragma unroll
            for (int ni = 0; ni < 8; ni++) {
                asm volatile(
                    "mma.sync.aligned.m16n8k8.row.col.f32.tf32.tf32.f32 "
                    "{%0,%1,%2,%3},{%4,%5,%6,%7},{%8,%9},{%0,%1,%2,%3};\n"
                    : "+f"(acc[mi][ni][0]), "+f"(acc[mi][ni][1]),
                      "+f"(acc[mi][ni][2]), "+f"(acc[mi][ni][3])
                    : "r"(a0), "r"(a1), "r"(a2), "r"(a3),
                      "r"(bf[ni][0]), "r"(bf[ni][1]));
            }
        }

        cur = (cur == NSTG - 1) ? 0 : cur + 1;
        nsl = (nsl == NSTG - 1) ? 0 : nsl + 1;
    }

    // epilogue: out[n][o][oh][ow]; m = n*4096 + p
#pragma unroll
    for (int mi = 0; mi < 4; mi++) {
#pragma unroll
        for (int h = 0; h < 2; h++) {
            const int m = bm + warpM * 64 + mi * 16 + qid + h * 8;
            const int nimg = m >> 12;
            const size_t base = ((size_t)nimg << 20) + (m & 4095);
#pragma unroll
            for (int ni = 0; ni < 8; ni++) {
                const int o = bnn + warpN * 64 + ni * 8 + kq * 2;
                out[base + (size_t)o * 4096]       = acc[mi][ni][h * 2 + 0];
                out[base + (size_t)(o + 1) * 4096] = acc[mi][ni][h * 2 + 1];
            }
        }
    }
}

// ---------------------------------------------------------------------------
extern "C" void kernel_launch(void* const* d_in, const int* in_sizes, int n_in,
                              void* d_out, int out_size) {
    const float* x      = (const float*)d_in[0];
    const float* offset = (const float*)d_in[1];
    const float* weight = (const float*)d_in[2];
    float* out = (float*)d_out;

    cudaFuncSetAttribute(gemm_kernel, cudaFuncAttributeMaxDynamicSharedMemorySize, GEMM_SMEM);

    transpose_x_kernel<<<dim3(128, 8, 8), dim3(32, 8)>>>(x);
    wt_kernel<<<KC, 256>>>(weight);
    gather_kernel<<<MTOT / 8, 256>>>(offset);
    gemm_kernel<<<dim3(OC / 128, MTOT / 128), 128, GEMM_SMEM>>>(out);
}